// round 10
// baseline (speedup 1.0000x reference)
#include <cuda_runtime.h>
#include <cuda_bf16.h>
#include <cstdint>

// Problem constants
#define BB   2048
#define NAG  8
#define ACT  16
#define HIDN 64
#define GRID_MMA 296   // 2 CTAs per SM (148 SMs)

// Scratch (__device__ globals: allowed)
__device__ float g_u[BB * NAG * HIDN];     // u[b,g,n]  (4 MB)
__device__ float g_w1aT[HIDN * 128];       // w1aT[k*128 + row]

// ---------------------------------------------------------------------------
__device__ __forceinline__ uint32_t pack_hi(float a, float b) {
    uint32_t r;
    asm("prmt.b32 %0, %1, %2, 0x7632;" : "=r"(r)
        : "r"(__float_as_uint(a)), "r"(__float_as_uint(b)));
    return r;
}
__device__ __forceinline__ uint32_t pack_lo(float a, float b) {
    float ha = __uint_as_float(__float_as_uint(a) & 0xffff0000u);
    float hb = __uint_as_float(__float_as_uint(b) & 0xffff0000u);
    float la = a - ha, lb = b - hb;
    uint32_t r;
    asm("cvt.rn.bf16x2.f32 %0, %1, %2;" : "=r"(r) : "f"(lb), "f"(la));
    return r;
}
__device__ __forceinline__ uint32_t smem_u32(const void* p) {
    uint32_t a;
    asm("{ .reg .u64 t; cvta.to.shared.u64 t, %1; cvt.u32.u64 %0, t; }" : "=r"(a) : "l"(p));
    return a;
}
__device__ __forceinline__ void fma4(float4& acc, float s, const float4 w) {
    acc.x = fmaf(s, w.x, acc.x);
    acc.y = fmaf(s, w.y, acc.y);
    acc.z = fmaf(s, w.z, acc.z);
    acc.w = fmaf(s, w.w, acc.w);
}

#define LDSM_X4(r, addr) \
    asm volatile("ldmatrix.sync.aligned.m8n8.x4.shared.b16 {%0,%1,%2,%3}, [%4];" \
        : "=r"((r)[0]), "=r"((r)[1]), "=r"((r)[2]), "=r"((r)[3]) : "r"(addr))
#define LDSM_X4_T(r, addr) \
    asm volatile("ldmatrix.sync.aligned.m8n8.x4.trans.shared.b16 {%0,%1,%2,%3}, [%4];" \
        : "=r"((r)[0]), "=r"((r)[1]), "=r"((r)[2]), "=r"((r)[3]) : "r"(addr))
#define MMA16816(c, a, b0, b1) \
    asm volatile("mma.sync.aligned.m16n8k16.row.col.f32.bf16.bf16.f32 " \
        "{%0,%1,%2,%3}, {%4,%5,%6,%7}, {%8,%9}, {%0,%1,%2,%3};" \
        : "+f"((c)[0]), "+f"((c)[1]), "+f"((c)[2]), "+f"((c)[3]) \
        : "r"((a)[0]), "r"((a)[1]), "r"((a)[2]), "r"((a)[3]), "r"(b0), "r"(b1))
#define CP_ASYNC16(dst, src) \
    asm volatile("cp.async.cg.shared.global [%0], [%1], 16;" :: "r"(dst), "l"(src) : "memory")
#define CP_COMMIT() asm volatile("cp.async.commit_group;" ::: "memory")
#define CP_WAIT0()  asm volatile("cp.async.wait_group 0;" ::: "memory")

// ---------------------------------------------------------------------------
// Kernel 1: layer-1 factorization (R8 version — measured best).
// 256 CTAs x 256 thr, 8 batches/CTA. Thread = (kq in 2, bl in 8, nq in 16).
// ---------------------------------------------------------------------------
__global__ void __launch_bounds__(256) prep_kernel(
    const float* __restrict__ hidden,   // [B, 8, 32]
    const float* __restrict__ actions,  // [B, 8, 16]
    const float* __restrict__ w1,       // [384, 64]
    const float* __restrict__ b1)       // [64]
{
    __shared__ float  sh[8 * 256];
    __shared__ float4 spart[8][16];
    __shared__ int    sidx[64];

    const int tid = threadIdx.x;
    const int b0  = blockIdx.x * 8;
    const float4* __restrict__ w1v = reinterpret_cast<const float4*>(w1);

    if (blockIdx.x == 0) {
        for (int e = tid; e < HIDN * 128; e += 256) {
            const int k   = e >> 7;
            const int row = e & 127;
            const int g   = row >> 4;
            const int a   = row & 15;
            g_w1aT[e] = __ldg(w1 + (g * 48 + 32 + a) * 64 + k);
        }
    }

    {
        const float4* hv = reinterpret_cast<const float4*>(hidden + (size_t)b0 * 256);
        float4* shv = reinterpret_cast<float4*>(sh);
        #pragma unroll
        for (int e = tid; e < 512; e += 256) shv[e] = __ldg(hv + e);
    }

    if (tid < 64) {
        const int bl = tid >> 3, g = tid & 7;
        const float* ag = actions + (size_t)(b0 + bl) * 128 + g * 16;
        float s = 0.f;
        #pragma unroll
        for (int a = 0; a < ACT; ++a) s = fmaf(__ldg(ag + a), (float)a, s);
        sidx[tid] = __float2int_rn(s);
    }
    __syncthreads();

    const int kq = tid >> 7;
    const int bl = (tid >> 4) & 7;
    const int nq = tid & 15;

    float4 acc = make_float4(0.f, 0.f, 0.f, 0.f);
    const float* h0 = sh + bl * 256 + kq * 128;
    #pragma unroll
    for (int j2 = 0; j2 < 4; ++j2) {
        const int j = kq * 4 + j2;
        #pragma unroll
        for (int i4 = 0; i4 < 8; ++i4) {
            const int wrow = j * 48 + i4 * 4;
            const float4 w0  = __ldg(w1v + (wrow + 0) * 16 + nq);
            const float4 w1_ = __ldg(w1v + (wrow + 1) * 16 + nq);
            const float4 w2_ = __ldg(w1v + (wrow + 2) * 16 + nq);
            const float4 w3_ = __ldg(w1v + (wrow + 3) * 16 + nq);
            const float4 h = *reinterpret_cast<const float4*>(h0 + j2 * 32 + i4 * 4);
            fma4(acc, h.x, w0); fma4(acc, h.y, w1_);
            fma4(acc, h.z, w2_); fma4(acc, h.w, w3_);
        }
    }
    if (kq == 1) spart[bl][nq] = acc;
    __syncthreads();

    if (kq == 0) {
        const float4 b1v = __ldg(reinterpret_cast<const float4*>(b1) + nq);
        const float4 p = spart[bl][nq];
        float4 base;
        base.x = acc.x + p.x + b1v.x;
        base.y = acc.y + p.y + b1v.y;
        base.z = acc.z + p.z + b1v.z;
        base.w = acc.w + p.w + b1v.w;

        float4 asum[NAG];
        float4 tot = make_float4(0.f, 0.f, 0.f, 0.f);
        #pragma unroll
        for (int g = 0; g < NAG; ++g) {
            asum[g] = __ldg(w1v + (g * 48 + 32 + sidx[bl * 8 + g]) * 16 + nq);
            tot.x += asum[g].x; tot.y += asum[g].y;
            tot.z += asum[g].z; tot.w += asum[g].w;
        }
        #pragma unroll
        for (int g = 0; g < NAG; ++g) {
            float4 v;
            v.x = base.x + tot.x - asum[g].x;
            v.y = base.y + tot.y - asum[g].y;
            v.z = base.z + tot.z - asum[g].z;
            v.w = base.w + tot.w - asum[g].w;
            *reinterpret_cast<float4*>(
                &g_u[(size_t)((b0 + bl) * NAG + g) * HIDN + nq * 4]) = v;
        }
    }
}

// ---------------------------------------------------------------------------
// Kernel 2: warp-specialized pipelined HMMA GEMM.
// 256 threads: warps 0-3 = consumers (mma + epilogue, rows 32w..32w+31 each),
// warps 4-7 = producers (each thread builds 1 of 128 A rows).
// Double-buffered A (2x32KB); B = [W_hi; W_lo] dedup (16KB); one sync/tile.
// Producer of tile s overlaps consumer mma of tile s-1.
// ---------------------------------------------------------------------------
#define SM_A0  0
#define SM_A1  32768
#define SM_B   65536     // 16384 bytes
#define SM_B2  81920
#define SM_W3  82176
#define SM_U   82432     // 2 x 2048-byte u slabs
#define SMEM_SZ 86528

__global__ void __launch_bounds__(256, 2) mma_kernel(
    const float* __restrict__ w2,   // [64, 64] (k-major)
    const float* __restrict__ b2,   // [64]
    const float* __restrict__ w3,   // [64]
    const float* __restrict__ b3,   // [1]
    float* __restrict__ out)        // [B, 128]
{
    extern __shared__ __align__(16) char dsm[];
    const uint32_t smAddr = smem_u32(dsm);
    const uint32_t smB = smAddr + SM_B;
    const uint32_t smU = smAddr + SM_U;
    float* sb2 = reinterpret_cast<float*>(dsm + SM_B2);
    float* sw3 = reinterpret_cast<float*>(dsm + SM_W3);

    const int tid  = threadIdx.x;
    const int wid  = tid >> 5;
    const int lane = tid & 31;
    const bool producer = (wid >= 4);

    if (tid < 64) {
        sb2[tid] = __ldg(b2 + tid);
        sw3[tid] = __ldg(w3 + tid);
    }
    const float b3v = __ldg(b3);

    // producers: prefetch u slab for first tile into slab 0
    if (producer) {
        const int ptid = tid - 128;
        CP_ASYNC16(smU + ptid * 16, g_u + (size_t)blockIdx.x * 512 + ptid * 4);
        CP_COMMIT();
        CP_WAIT0();
    }

    // build B = [W_hi; W_lo] (128 k-rows x 64 n), xor-swizzled (all threads)
    for (int e = tid; e < 128 * 32; e += 256) {
        const int kk = e >> 5;
        const int nw = e & 31;
        const int k  = kk & 63;
        const float2 f = __ldg(reinterpret_cast<const float2*>(w2 + k * 64 + 2 * nw));
        const uint32_t word = (kk < 64) ? pack_hi(f.x, f.y) : pack_lo(f.x, f.y);
        const int nc = nw >> 2;
        const uint32_t byte = (uint32_t)kk * 128u + (uint32_t)((nc ^ (kk & 7)) << 4)
                            + (uint32_t)((nw & 3) << 2);
        *reinterpret_cast<uint32_t*>(dsm + SM_B + byte) = word;
    }
    __syncthreads();

    // ---- consumer lane decomposition ----
    const int g2  = lane >> 4;
    const int gh  = (lane >> 3) & 1;
    const int lr  = lane & 7;
    const int grp = lane >> 2;
    const int tig = lane & 3;

    uint32_t aB[2][2];
    #pragma unroll
    for (int buf = 0; buf < 2; ++buf)
        #pragma unroll
        for (int mt = 0; mt < 2; ++mt)
            aB[buf][mt] = smAddr + (uint32_t)(buf * 32768)
                        + (uint32_t)(32 * wid + 16 * mt + 8 * gh + lr) * 256u;

    const int nadd = lane >> 4;
    const uint32_t bBase = smB + (uint32_t)(8 * ((lane >> 3) & 1) + lr) * 128u;
    uint32_t nxor[4];
    #pragma unroll
    for (int np = 0; np < 4; ++np)
        nxor[np] = (uint32_t)(((2 * np + nadd) ^ lr) << 4);

    // ---- producer row decomposition ----
    const int prow  = tid - 128;                  // 0..127 (producers only)
    const int pgq   = prow >> 4;
    const uint32_t prbase = (uint32_t)prow * 256u;
    const int prx = prow & 7;

    const int n_t = (BB - 1 - blockIdx.x) / GRID_MMA + 1;

    for (int s = 0; s <= n_t; ++s) {
        if (producer && s < n_t) {
            const int b   = blockIdx.x + s * GRID_MMA;
            const int cur = s & 1;
            // build A': x1[row,k] = relu(u_s[g,k] + w1aT[k,row])
            const float4* us =
                reinterpret_cast<const float4*>(dsm + SM_U + cur * 2048) + pgq * 16;
            char* bufA = dsm + cur * 32768;
            #pragma unroll
            for (int c8 = 0; c8 < 8; ++c8) {
                const int k0 = c8 * 8;
                const float4 u0 = us[c8 * 2];
                const float4 u1 = us[c8 * 2 + 1];
                float x[8];
                x[0] = u0.x; x[1] = u0.y; x[2] = u0.z; x[3] = u0.w;
                x[4] = u1.x; x[5] = u1.y; x[6] = u1.z; x[7] = u1.w;
                #pragma unroll
                for (int j = 0; j < 8; ++j)
                    x[j] = fmaxf(x[j] + __ldg(g_w1aT + (k0 + j) * 128 + prow), 0.f);

                uint4 hi4, lo4;
                hi4.x = pack_hi(x[0], x[1]); hi4.y = pack_hi(x[2], x[3]);
                hi4.z = pack_hi(x[4], x[5]); hi4.w = pack_hi(x[6], x[7]);
                lo4.x = pack_lo(x[0], x[1]); lo4.y = pack_lo(x[2], x[3]);
                lo4.z = pack_lo(x[4], x[5]); lo4.w = pack_lo(x[6], x[7]);

                *reinterpret_cast<uint4*>(bufA + prbase + ((c8 ^ prx) << 4))       = hi4;
                *reinterpret_cast<uint4*>(bufA + prbase + (((8 + c8) ^ prx) << 4)) = lo4;
            }
            // prefetch next tile's u slab into the other buffer
            const int bn = b + GRID_MMA;
            if (bn < BB) {
                CP_ASYNC16(smU + (cur ^ 1) * 2048 + prow * 16,
                           g_u + (size_t)bn * 512 + prow * 4);
                CP_COMMIT();
            }
        }

        if (!producer && s > 0) {
            const int b   = blockIdx.x + (s - 1) * GRID_MMA;
            const int buf = (s - 1) & 1;

            float acc[2][8][4];
            #pragma unroll
            for (int mt = 0; mt < 2; ++mt)
                #pragma unroll
                for (int nt = 0; nt < 8; ++nt)
                    #pragma unroll
                    for (int q = 0; q < 4; ++q) acc[mt][nt][q] = 0.f;

            #pragma unroll
            for (int kp = 0; kp < 4; ++kp) {
                uint32_t ah[2][4], al[2][4];
                #pragma unroll
                for (int mt = 0; mt < 2; ++mt) {
                    LDSM_X4(ah[mt], aB[buf][mt] + (uint32_t)(((2 * kp + g2) ^ lr) << 4));
                    LDSM_X4(al[mt], aB[buf][mt] + (uint32_t)(((8 + 2 * kp + g2) ^ lr) << 4));
                }
                uint32_t bh[4][4], blo[4][4];
                #pragma unroll
                for (int np = 0; np < 4; ++np) {
                    LDSM_X4_T(bh[np],  bBase + (uint32_t)(kp * 2048)       + nxor[np]);
                    LDSM_X4_T(blo[np], bBase + (uint32_t)((4 + kp) * 2048) + nxor[np]);
                }
                #pragma unroll
                for (int mt = 0; mt < 2; ++mt) {
                    #pragma unroll
                    for (int np = 0; np < 4; ++np) {
                        MMA16816(acc[mt][2 * np + 0], ah[mt], bh[np][0],  bh[np][1]);
                        MMA16816(acc[mt][2 * np + 1], ah[mt], bh[np][2],  bh[np][3]);
                        MMA16816(acc[mt][2 * np + 0], al[mt], bh[np][0],  bh[np][1]);
                        MMA16816(acc[mt][2 * np + 1], al[mt], bh[np][2],  bh[np][3]);
                        MMA16816(acc[mt][2 * np + 0], ah[mt], blo[np][0], blo[np][1]);
                        MMA16816(acc[mt][2 * np + 1], ah[mt], blo[np][2], blo[np][3]);
                    }
                }
            }

            // epilogue
            float o[2][2] = {{0.f, 0.f}, {0.f, 0.f}};
            #pragma unroll
            for (int nt = 0; nt < 8; ++nt) {
                const int col = nt * 8 + 2 * tig;
                const float2 bb = *reinterpret_cast<const float2*>(sb2 + col);
                const float2 ww = *reinterpret_cast<const float2*>(sw3 + col);
                #pragma unroll
                for (int mt = 0; mt < 2; ++mt) {
                    o[mt][0] = fmaf(fmaxf(acc[mt][nt][0] + bb.x, 0.f), ww.x, o[mt][0]);
                    o[mt][0] = fmaf(fmaxf(acc[mt][nt][1] + bb.y, 0.f), ww.y, o[mt][0]);
                    o[mt][1] = fmaf(fmaxf(acc[mt][nt][2] + bb.x, 0.f), ww.x, o[mt][1]);
                    o[mt][1] = fmaf(fmaxf(acc[mt][nt][3] + bb.y, 0.f), ww.y, o[mt][1]);
                }
            }
            #pragma unroll
            for (int mt = 0; mt < 2; ++mt) {
                #pragma unroll
                for (int rh = 0; rh < 2; ++rh) {
                    float v = o[mt][rh];
                    v += __shfl_xor_sync(0xffffffffu, v, 1);
                    v += __shfl_xor_sync(0xffffffffu, v, 2);
                    if (tig == 0) {
                        const int row = 32 * wid + 16 * mt + 8 * rh + grp;
                        out[b * 128 + row] = v + b3v;
                    }
                }
            }
        }

        // producers: ensure this iteration's prefetch landed before the barrier
        if (producer) CP_WAIT0();
        __syncthreads();
    }
}

// ---------------------------------------------------------------------------
extern "C" void kernel_launch(void* const* d_in, const int* in_sizes, int n_in,
                              void* d_out, int out_size) {
    const float* hidden  = (const float*)d_in[0];
    const float* actions = (const float*)d_in[1];
    const float* w1      = (const float*)d_in[2];
    const float* b1      = (const float*)d_in[3];
    const float* w2      = (const float*)d_in[4];
    const float* b2      = (const float*)d_in[5];
    const float* w3      = (const float*)d_in[6];
    const float* b3      = (const float*)d_in[7];
    float* out = (float*)d_out;

    cudaFuncSetAttribute(mma_kernel, cudaFuncAttributeMaxDynamicSharedMemorySize, SMEM_SZ);

    prep_kernel<<<BB / 8, 256>>>(hidden, actions, w1, b1);
    mma_kernel<<<GRID_MMA, 256, SMEM_SZ>>>(w2, b2, w3, b3, out);
}

// round 11
// speedup vs baseline: 1.1222x; 1.1222x over previous
#include <cuda_runtime.h>
#include <cuda_bf16.h>
#include <cstdint>

// Problem constants
#define BB   2048
#define NAG  8
#define ACT  16
#define HIDN 64
#define GRID_MMA 444   // 3 CTAs per SM (148 SMs)

// Scratch (__device__ globals: allowed)
__device__ float g_u[BB * NAG * HIDN];     // u[b,g,n]  (4 MB)
__device__ float g_w1aT[HIDN * 128];       // w1aT[k*128 + row]

// ---------------------------------------------------------------------------
__device__ __forceinline__ uint32_t pack_hi(float a, float b) {
    uint32_t r;
    asm("prmt.b32 %0, %1, %2, 0x7632;" : "=r"(r)
        : "r"(__float_as_uint(a)), "r"(__float_as_uint(b)));
    return r;
}
__device__ __forceinline__ uint32_t pack_lo(float a, float b) {
    float ha = __uint_as_float(__float_as_uint(a) & 0xffff0000u);
    float hb = __uint_as_float(__float_as_uint(b) & 0xffff0000u);
    float la = a - ha, lb = b - hb;
    uint32_t r;
    asm("cvt.rn.bf16x2.f32 %0, %1, %2;" : "=r"(r) : "f"(lb), "f"(la));
    return r;
}
__device__ __forceinline__ uint32_t smem_u32(const void* p) {
    uint32_t a;
    asm("{ .reg .u64 t; cvta.to.shared.u64 t, %1; cvt.u32.u64 %0, t; }" : "=r"(a) : "l"(p));
    return a;
}
__device__ __forceinline__ void fma4(float4& acc, float s, const float4 w) {
    acc.x = fmaf(s, w.x, acc.x);
    acc.y = fmaf(s, w.y, acc.y);
    acc.z = fmaf(s, w.z, acc.z);
    acc.w = fmaf(s, w.w, acc.w);
}

#define LDSM_X4(r, addr) \
    asm volatile("ldmatrix.sync.aligned.m8n8.x4.shared.b16 {%0,%1,%2,%3}, [%4];" \
        : "=r"((r)[0]), "=r"((r)[1]), "=r"((r)[2]), "=r"((r)[3]) : "r"(addr))
#define LDSM_X4_T(r, addr) \
    asm volatile("ldmatrix.sync.aligned.m8n8.x4.trans.shared.b16 {%0,%1,%2,%3}, [%4];" \
        : "=r"((r)[0]), "=r"((r)[1]), "=r"((r)[2]), "=r"((r)[3]) : "r"(addr))
#define MMA16816(c, a, b0, b1) \
    asm volatile("mma.sync.aligned.m16n8k16.row.col.f32.bf16.bf16.f32 " \
        "{%0,%1,%2,%3}, {%4,%5,%6,%7}, {%8,%9}, {%0,%1,%2,%3};" \
        : "+f"((c)[0]), "+f"((c)[1]), "+f"((c)[2]), "+f"((c)[3]) \
        : "r"((a)[0]), "r"((a)[1]), "r"((a)[2]), "r"((a)[3]), "r"(b0), "r"(b1))
#define CP_ASYNC16(dst, src) \
    asm volatile("cp.async.cg.shared.global [%0], [%1], 16;" :: "r"(dst), "l"(src) : "memory")
#define CP_COMMIT() asm volatile("cp.async.commit_group;" ::: "memory")
#define CP_WAIT0()  asm volatile("cp.async.wait_group 0;" ::: "memory")

// ---------------------------------------------------------------------------
// Kernel 1: layer-1 factorization (R8 version — measured best, ~9us).
// 256 CTAs x 256 thr, 8 batches/CTA. Thread = (kq in 2, bl in 8, nq in 16):
// kq halves the hidden dot; partials combined via SMEM. One-hot actions =
// exact row gather. Emits column-major g_w1aT for the mma build phase.
// ---------------------------------------------------------------------------
__global__ void __launch_bounds__(256) prep_kernel(
    const float* __restrict__ hidden,   // [B, 8, 32]
    const float* __restrict__ actions,  // [B, 8, 16]
    const float* __restrict__ w1,       // [384, 64]
    const float* __restrict__ b1)       // [64]
{
    __shared__ float  sh[8 * 256];
    __shared__ float4 spart[8][16];
    __shared__ int    sidx[64];

    const int tid = threadIdx.x;
    const int b0  = blockIdx.x * 8;
    const float4* __restrict__ w1v = reinterpret_cast<const float4*>(w1);

    if (blockIdx.x == 0) {
        for (int e = tid; e < HIDN * 128; e += 256) {
            const int k   = e >> 7;
            const int row = e & 127;
            const int g   = row >> 4;
            const int a   = row & 15;
            g_w1aT[e] = __ldg(w1 + (g * 48 + 32 + a) * 64 + k);
        }
    }

    {
        const float4* hv = reinterpret_cast<const float4*>(hidden + (size_t)b0 * 256);
        float4* shv = reinterpret_cast<float4*>(sh);
        #pragma unroll
        for (int e = tid; e < 512; e += 256) shv[e] = __ldg(hv + e);
    }

    if (tid < 64) {
        const int bl = tid >> 3, g = tid & 7;
        const float* ag = actions + (size_t)(b0 + bl) * 128 + g * 16;
        float s = 0.f;
        #pragma unroll
        for (int a = 0; a < ACT; ++a) s = fmaf(__ldg(ag + a), (float)a, s);
        sidx[tid] = __float2int_rn(s);
    }
    __syncthreads();

    const int kq = tid >> 7;
    const int bl = (tid >> 4) & 7;
    const int nq = tid & 15;

    float4 acc = make_float4(0.f, 0.f, 0.f, 0.f);
    const float* h0 = sh + bl * 256 + kq * 128;
    #pragma unroll
    for (int j2 = 0; j2 < 4; ++j2) {
        const int j = kq * 4 + j2;
        #pragma unroll
        for (int i4 = 0; i4 < 8; ++i4) {
            const int wrow = j * 48 + i4 * 4;
            const float4 w0  = __ldg(w1v + (wrow + 0) * 16 + nq);
            const float4 w1_ = __ldg(w1v + (wrow + 1) * 16 + nq);
            const float4 w2_ = __ldg(w1v + (wrow + 2) * 16 + nq);
            const float4 w3_ = __ldg(w1v + (wrow + 3) * 16 + nq);
            const float4 h = *reinterpret_cast<const float4*>(h0 + j2 * 32 + i4 * 4);
            fma4(acc, h.x, w0); fma4(acc, h.y, w1_);
            fma4(acc, h.z, w2_); fma4(acc, h.w, w3_);
        }
    }
    if (kq == 1) spart[bl][nq] = acc;
    __syncthreads();

    if (kq == 0) {
        const float4 b1v = __ldg(reinterpret_cast<const float4*>(b1) + nq);
        const float4 p = spart[bl][nq];
        float4 base;
        base.x = acc.x + p.x + b1v.x;
        base.y = acc.y + p.y + b1v.y;
        base.z = acc.z + p.z + b1v.z;
        base.w = acc.w + p.w + b1v.w;

        float4 asum[NAG];
        float4 tot = make_float4(0.f, 0.f, 0.f, 0.f);
        #pragma unroll
        for (int g = 0; g < NAG; ++g) {
            asum[g] = __ldg(w1v + (g * 48 + 32 + sidx[bl * 8 + g]) * 16 + nq);
            tot.x += asum[g].x; tot.y += asum[g].y;
            tot.z += asum[g].z; tot.w += asum[g].w;
        }
        #pragma unroll
        for (int g = 0; g < NAG; ++g) {
            float4 v;
            v.x = base.x + tot.x - asum[g].x;
            v.y = base.y + tot.y - asum[g].y;
            v.z = base.z + tot.z - asum[g].z;
            v.w = base.w + tot.w - asum[g].w;
            *reinterpret_cast<float4*>(
                &g_u[(size_t)((b0 + bl) * NAG + g) * HIDN + nq * 4]) = v;
        }
    }
}

// ---------------------------------------------------------------------------
// Kernel 2: persistent HMMA GEMM (R9 version — measured best, 26.75us).
// cp.async double-buffered u prefetch + B-dedup k-loop (48 LDSM/tile).
// B SMEM stores [W_hi; W_lo] (16 KB). Per physical k-chunk kp: load
// A_hi, A_lo, B_hi, B_lo once, issue all 3 split products.
// ---------------------------------------------------------------------------
#define SM_A   0
#define SM_B   32768     // 16384 bytes: rows 0-63 = W_hi, rows 64-127 = W_lo
#define SM_B2  49152
#define SM_W3  49408
#define SM_U   49664     // 2 x 2048-byte u slabs
#define SMEM_SZ 53760

__global__ void __launch_bounds__(128, 3) mma_kernel(
    const float* __restrict__ w2,   // [64, 64] (k-major)
    const float* __restrict__ b2,   // [64]
    const float* __restrict__ w3,   // [64]
    const float* __restrict__ b3,   // [1]
    float* __restrict__ out)        // [B, 128]
{
    extern __shared__ __align__(16) char dsm[];
    const uint32_t smAddr = smem_u32(dsm);
    const uint32_t smA = smAddr + SM_A;
    const uint32_t smB = smAddr + SM_B;
    const uint32_t smU = smAddr + SM_U;
    float* sb2 = reinterpret_cast<float*>(dsm + SM_B2);
    float* sw3 = reinterpret_cast<float*>(dsm + SM_W3);

    const int tid  = threadIdx.x;
    const int w    = tid >> 5;
    const int lane = tid & 31;

    if (tid < 64) {
        sb2[tid] = __ldg(b2 + tid);
        sw3[tid] = __ldg(w3 + tid);
    }
    const float b3v = __ldg(b3);

    // prologue: prefetch u slab for first tile into buffer 0
    CP_ASYNC16(smU + tid * 16, g_u + (size_t)blockIdx.x * 512 + tid * 4);
    CP_COMMIT();

    // build B = [W_hi; W_lo] (128 k-rows x 64 n), xor-swizzled
    for (int e = tid; e < 128 * 32; e += 128) {
        const int kk = e >> 5;
        const int nw = e & 31;
        const int k  = kk & 63;
        const float2 f = __ldg(reinterpret_cast<const float2*>(w2 + k * 64 + 2 * nw));
        const uint32_t word = (kk < 64) ? pack_hi(f.x, f.y) : pack_lo(f.x, f.y);
        const int nc = nw >> 2;
        const uint32_t byte = (uint32_t)kk * 128u + (uint32_t)((nc ^ (kk & 7)) << 4)
                            + (uint32_t)((nw & 3) << 2);
        *reinterpret_cast<uint32_t*>(dsm + SM_B + byte) = word;
    }

    // per-lane ldmatrix address precompute
    const int g2  = lane >> 4;
    const int gh  = (lane >> 3) & 1;
    const int lr  = lane & 7;
    const int grp = lane >> 2;
    const int tig = lane & 3;

    uint32_t aBase[2];
    #pragma unroll
    for (int mt = 0; mt < 2; ++mt)
        aBase[mt] = smA + (uint32_t)(32 * w + 16 * mt + 8 * gh + lr) * 256u;

    const int nadd = lane >> 4;
    const uint32_t bBase = smB + (uint32_t)(8 * ((lane >> 3) & 1) + lr) * 128u;
    uint32_t nxor[4];
    #pragma unroll
    for (int np = 0; np < 4; ++np)
        nxor[np] = (uint32_t)(((2 * np + nadd) ^ lr) << 4);

    const int row_ga = tid;
    const int gq     = row_ga >> 4;
    const uint32_t rbase = (uint32_t)row_ga * 256u;
    const int rx = row_ga & 7;

    int it = 0;
    for (int b = blockIdx.x; b < BB; b += GRID_MMA) {
        const int cur = it & 1;

        CP_WAIT0();
        __syncthreads();

        // build A': x1[row,k] = relu(u_s[g,k] + w1aT[k,row]); hi chunks 0-7, lo 8-15
        const float4* us = reinterpret_cast<const float4*>(dsm + SM_U + cur * 2048) + gq * 16;
        #pragma unroll
        for (int c8 = 0; c8 < 8; ++c8) {
            const int k0 = c8 * 8;
            const float4 u0 = us[c8 * 2];
            const float4 u1 = us[c8 * 2 + 1];
            float x[8];
            x[0] = u0.x; x[1] = u0.y; x[2] = u0.z; x[3] = u0.w;
            x[4] = u1.x; x[5] = u1.y; x[6] = u1.z; x[7] = u1.w;
            #pragma unroll
            for (int j = 0; j < 8; ++j)
                x[j] = fmaxf(x[j] + __ldg(g_w1aT + (k0 + j) * 128 + row_ga), 0.f);

            uint4 hi4, lo4;
            hi4.x = pack_hi(x[0], x[1]); hi4.y = pack_hi(x[2], x[3]);
            hi4.z = pack_hi(x[4], x[5]); hi4.w = pack_hi(x[6], x[7]);
            lo4.x = pack_lo(x[0], x[1]); lo4.y = pack_lo(x[2], x[3]);
            lo4.z = pack_lo(x[4], x[5]); lo4.w = pack_lo(x[6], x[7]);

            *reinterpret_cast<uint4*>(dsm + SM_A + rbase + ((c8 ^ rx) << 4))       = hi4;
            *reinterpret_cast<uint4*>(dsm + SM_A + rbase + (((8 + c8) ^ rx) << 4)) = lo4;
        }

        // prefetch u slab for the next tile
        {
            int bn = b + GRID_MMA;
            if (bn >= BB) bn = b;
            CP_ASYNC16(smU + (cur ^ 1) * 2048 + tid * 16,
                       g_u + (size_t)bn * 512 + tid * 4);
            CP_COMMIT();
        }
        __syncthreads();

        // mma phase: 4 physical k-chunks x 3 split products
        float acc[2][8][4];
        #pragma unroll
        for (int mt = 0; mt < 2; ++mt)
            #pragma unroll
            for (int nt = 0; nt < 8; ++nt)
                #pragma unroll
                for (int q = 0; q < 4; ++q) acc[mt][nt][q] = 0.f;

        #pragma unroll
        for (int kp = 0; kp < 4; ++kp) {
            uint32_t ah[2][4], al[2][4];
            #pragma unroll
            for (int mt = 0; mt < 2; ++mt) {
                LDSM_X4(ah[mt], aBase[mt] + (uint32_t)(((2 * kp + g2) ^ lr) << 4));
                LDSM_X4(al[mt], aBase[mt] + (uint32_t)(((8 + 2 * kp + g2) ^ lr) << 4));
            }
            uint32_t bh[4][4], blo[4][4];
            #pragma unroll
            for (int np = 0; np < 4; ++np) {
                LDSM_X4_T(bh[np],  bBase + (uint32_t)(kp * 2048)       + nxor[np]);
                LDSM_X4_T(blo[np], bBase + (uint32_t)((4 + kp) * 2048) + nxor[np]);
            }
            #pragma unroll
            for (int mt = 0; mt < 2; ++mt) {
                #pragma unroll
                for (int np = 0; np < 4; ++np) {
                    MMA16816(acc[mt][2 * np + 0], ah[mt], bh[np][0],  bh[np][1]);
                    MMA16816(acc[mt][2 * np + 1], ah[mt], bh[np][2],  bh[np][3]);
                    MMA16816(acc[mt][2 * np + 0], al[mt], bh[np][0],  bh[np][1]);
                    MMA16816(acc[mt][2 * np + 1], al[mt], bh[np][2],  bh[np][3]);
                    MMA16816(acc[mt][2 * np + 0], ah[mt], blo[np][0], blo[np][1]);
                    MMA16816(acc[mt][2 * np + 1], ah[mt], blo[np][2], blo[np][3]);
                }
            }
        }

        // epilogue: +b2, relu, dot w3, reduce over tig, store
        float o[2][2] = {{0.f, 0.f}, {0.f, 0.f}};
        #pragma unroll
        for (int nt = 0; nt < 8; ++nt) {
            const int col = nt * 8 + 2 * tig;
            const float2 bb = *reinterpret_cast<const float2*>(sb2 + col);
            const float2 ww = *reinterpret_cast<const float2*>(sw3 + col);
            #pragma unroll
            for (int mt = 0; mt < 2; ++mt) {
                o[mt][0] = fmaf(fmaxf(acc[mt][nt][0] + bb.x, 0.f), ww.x, o[mt][0]);
                o[mt][0] = fmaf(fmaxf(acc[mt][nt][1] + bb.y, 0.f), ww.y, o[mt][0]);
                o[mt][1] = fmaf(fmaxf(acc[mt][nt][2] + bb.x, 0.f), ww.x, o[mt][1]);
                o[mt][1] = fmaf(fmaxf(acc[mt][nt][3] + bb.y, 0.f), ww.y, o[mt][1]);
            }
        }
        #pragma unroll
        for (int mt = 0; mt < 2; ++mt) {
            #pragma unroll
            for (int rh = 0; rh < 2; ++rh) {
                float v = o[mt][rh];
                v += __shfl_xor_sync(0xffffffffu, v, 1);
                v += __shfl_xor_sync(0xffffffffu, v, 2);
                if (tig == 0) {
                    const int row = 32 * w + 16 * mt + 8 * rh + grp;
                    out[b * 128 + row] = v + b3v;
                }
            }
        }
        ++it;
    }
}

// ---------------------------------------------------------------------------
extern "C" void kernel_launch(void* const* d_in, const int* in_sizes, int n_in,
                              void* d_out, int out_size) {
    const float* hidden  = (const float*)d_in[0];
    const float* actions = (const float*)d_in[1];
    const float* w1      = (const float*)d_in[2];
    const float* b1      = (const float*)d_in[3];
    const float* w2      = (const float*)d_in[4];
    const float* b2      = (const float*)d_in[5];
    const float* w3      = (const float*)d_in[6];
    const float* b3      = (const float*)d_in[7];
    float* out = (float*)d_out;

    cudaFuncSetAttribute(mma_kernel, cudaFuncAttributeMaxDynamicSharedMemorySize, SMEM_SZ);

    prep_kernel<<<BB / 8, 256>>>(hidden, actions, w1, b1);
    mma_kernel<<<GRID_MMA, 128, SMEM_SZ>>>(w2, b2, w3, b3, out);
}